// round 1
// baseline (speedup 1.0000x reference)
#include <cuda_runtime.h>
#include <cstdint>

// Elementwise: out = (x+2) + 3x - (x-1)*(x/2)  ==  -0.5*x^2 + 4.5*x + 2
// N = 8192*16384 = 134217728, divisible by 4 -> float4 with no tail.

__global__ void fused_elem_kernel(const float4* __restrict__ x,
                                  float4* __restrict__ out,
                                  int n_vec) {
    int i = blockIdx.x * blockDim.x + threadIdx.x;
    if (i < n_vec) {
        float4 v = x[i];
        float4 r;
        r.x = fmaf(v.x, fmaf(v.x, -0.5f, 4.5f), 2.0f);
        r.y = fmaf(v.y, fmaf(v.y, -0.5f, 4.5f), 2.0f);
        r.z = fmaf(v.z, fmaf(v.z, -0.5f, 4.5f), 2.0f);
        r.w = fmaf(v.w, fmaf(v.w, -0.5f, 4.5f), 2.0f);
        out[i] = r;
    }
}

extern "C" void kernel_launch(void* const* d_in, const int* in_sizes, int n_in,
                              void* d_out, int out_size) {
    const float* x = (const float*)d_in[0];
    float* out = (float*)d_out;
    int n = in_sizes[0];            // 134217728
    int n_vec = n >> 2;             // 33554432 (n divisible by 4)

    const int threads = 256;
    int blocks = (n_vec + threads - 1) / threads;
    fused_elem_kernel<<<blocks, threads>>>((const float4*)x, (float4*)out, n_vec);
}